// round 11
// baseline (speedup 1.0000x reference)
#include <cuda_runtime.h>
#include <cuda_fp16.h>
#include <cstdint>

// ---------------- problem constants ----------------
#define CCH   200               // channels
#define NC8   25                // uint4 (8-half) chunks per position
#define D3    16
#define H3    60
#define W3    80
#define P3    (D3*H3*W3)        // 76800
#define H2    120
#define W2    160
#define P2    (H2*W2)           // 19200
#define XDIM  60
#define YDIM  36
#define ZDIM  60
#define NVOX  (XDIM*YDIM*ZDIM)  // 129600
#define NB    2
#define VPB   10                // voxels per block
#define ZCH   (ZDIM/VPB)        // 6

#define T3TILES (P3/32)         // 2400
#define T2TILES (P2/32)         // 600
#define GP2BASE (NB*P3)         // global position base of 2D region

// fused channel-last fp16 scratch, 400B per position:
// [3D: b*P3+pos][2D: NB*P3 + b*P2+pos]
__device__ __align__(16) __half g_s[(size_t)(NB*(P3+P2)) * CCH];   // 76.8 MB

// ---------------- pass 1: fused add + transpose (C,P)->(P,C), fp32->fp16 ---
__global__ void transpose_add_kernel(const float* __restrict__ a3,
                                     const float* __restrict__ b3,
                                     const float* __restrict__ a2,
                                     const float* __restrict__ b2,
                                     __half* __restrict__ ds)
{
    __shared__ float tile[32][33];
    int pt = blockIdx.x;
    const int ct = blockIdx.y;
    const int batch = blockIdx.z;

    const float *ab, *bb;
    __half* db;
    int P;
    if (pt < T3TILES) {
        P  = P3;
        ab = a3 + (size_t)batch * CCH * P3;
        bb = b3 + (size_t)batch * CCH * P3;
        db = ds + (size_t)(batch * P3) * CCH;
    } else {
        pt -= T3TILES;
        P  = P2;
        ab = a2 + (size_t)batch * CCH * P2;
        bb = b2 + (size_t)batch * CCH * P2;
        db = ds + (size_t)(GP2BASE + batch * P2) * CCH;
    }

    const int p0 = pt * 32, c0 = ct * 32;
    const int tx = threadIdx.x, ty = threadIdx.y;   // 32 x 8

    #pragma unroll
    for (int i = 0; i < 32; i += 8) {
        int c = c0 + ty + i;
        int p = p0 + tx;
        if (c < CCH)
            tile[ty + i][tx] = ab[(size_t)c * P + p] + bb[(size_t)c * P + p];
    }
    __syncthreads();
    #pragma unroll
    for (int i = 0; i < 32; i += 8) {
        int p = p0 + ty + i;
        int c = c0 + tx;
        if (c < CCH)
            db[(size_t)p * CCH + c] = __float2half_rn(tile[tx][ty + i]);
    }
}

// ---------------- pass 2: 2 warps per voxel, 6 taps each ----------------
// block = 640 threads = 20 warps = 10 voxels
__global__ void __launch_bounds__(640, 2) sample_kernel(const float* __restrict__ pp,
                                                        float* __restrict__ out)
{
    __shared__ int2  sm_tap[VPB][12];    // {uint4-chunk base, weight bits}
    __shared__ float stA[VPB][204];      // taps 0-5
    __shared__ float stB[VPB][204];      // taps 6-11

    const int bid = blockIdx.x;
    const int zc  = bid % ZCH;
    int rest      = bid / ZCH;
    const int y   = rest % YDIM; rest /= YDIM;
    const int x   = rest % XDIM;
    const int b   = rest / XDIM;
    const int z0  = zc * VPB;
    const int tid = threadIdx.x;

    // ---------- Phase A: tap setup (one thread per voxel-tap) ----------
    if (tid < VPB * 12) {
        const int q = tid / 12;
        const int t = tid % 12;          // 0..7 = 3D, 8..11 = 2D
        const int z = z0 + q;
        const int v = x * (ZDIM * YDIM) + z * YDIM + y;
        const float* g = pp + ((size_t)b * NVOX + v) * 3;
        const float px = __ldg(g + 0), py = __ldg(g + 1);

        int gpos; float weight;
        if (t < 8) {
            const float pz = __ldg(g + 2);
            const float gx = (px + 1.f) * 0.5f * (W3 - 1);
            const float gy = (py + 1.f) * 0.5f * (H3 - 1);
            const float gz = (pz + 1.f) * 0.5f * (D3 - 1);
            const float fx = floorf(gx), fy = floorf(gy), fz = floorf(gz);
            const float wx = gx - fx, wy = gy - fy, wz = gz - fz;
            const int dx = t & 1, dy = (t >> 1) & 1, dz = (t >> 2) & 1;
            const int xi = (int)fx + dx, yi = (int)fy + dy, zi = (int)fz + dz;
            const bool valid = (xi >= 0) & (xi < W3) & (yi >= 0) & (yi < H3) &
                               (zi >= 0) & (zi < D3);
            const int xc = min(max(xi, 0), W3 - 1);
            const int yc = min(max(yi, 0), H3 - 1);
            const int zcv = min(max(zi, 0), D3 - 1);
            gpos = b * P3 + (zcv * H3 + yc) * W3 + xc;
            float w = (dx ? wx : 1.f - wx) * (dy ? wy : 1.f - wy) *
                      (dz ? wz : 1.f - wz);
            weight = valid ? w : 0.f;
        } else {
            const float gx = (px + 1.f) * 0.5f * (W2 - 1);
            const float gy = (py + 1.f) * 0.5f * (H2 - 1);
            const float fx = floorf(gx), fy = floorf(gy);
            const float wx = gx - fx, wy = gy - fy;
            const int tt = t - 8;
            const int dx = tt & 1, dy = (tt >> 1) & 1;
            const int xi = (int)fx + dx, yi = (int)fy + dy;
            const bool valid = (xi >= 0) & (xi < W2) & (yi >= 0) & (yi < H2);
            const int xc = min(max(xi, 0), W2 - 1);
            const int yc = min(max(yi, 0), H2 - 1);
            gpos = GP2BASE + b * P2 + yc * W2 + xc;
            float w = (dx ? wx : 1.f - wx) * (dy ? wy : 1.f - wy);
            weight = valid ? w : 0.f;
        }
        sm_tap[q][t] = make_int2(gpos * NC8, __float_as_int(weight));
    }
    __syncthreads();

    // ---------- Phase B: warp w -> voxel w>>1, tap half w&1 ----------
    {
        const int warp = tid >> 5;
        const int lane = tid & 31;
        const int q    = warp >> 1;
        const int h    = warp & 1;       // 0: taps 0-5, 1: taps 6-11
        const uint4* gs = (const uint4*)g_s;

        if (lane < NC8) {
            const int t0 = h * 6;
            float ax = 0.f, ay = 0.f, az = 0.f, aw = 0.f;
            float bx = 0.f, by = 0.f, bz = 0.f, bw = 0.f;
            #pragma unroll
            for (int t = 0; t < 6; t++) {
                const int2 tap = sm_tap[q][t0 + t];   // warp-uniform LDS.64
                const uint4 vv = gs[(size_t)tap.x + lane];
                const float w  = __int_as_float(tap.y);
                const __half2* hh = (const __half2*)&vv;
                const float2 f0 = __half22float2(hh[0]);
                const float2 f1 = __half22float2(hh[1]);
                const float2 f2 = __half22float2(hh[2]);
                const float2 f3 = __half22float2(hh[3]);
                ax += w * f0.x; ay += w * f0.y;
                az += w * f1.x; aw += w * f1.y;
                bx += w * f2.x; by += w * f2.y;
                bz += w * f3.x; bw += w * f3.y;
            }
            float (*st)[204] = h ? stB : stA;
            *(float4*)&st[q][lane * 8]     = make_float4(ax, ay, az, aw);
            *(float4*)&st[q][lane * 8 + 4] = make_float4(bx, by, bz, bw);
        }
    }
    __syncthreads();

    // ---------- Phase C: add halves + coalesced write-out ----------
    float* ob = out + (size_t)b * CCH * NVOX +
                ((size_t)x * YDIM + y) * ZDIM + z0;
    for (int idx = tid; idx < CCH * (VPB / 2); idx += 640) {
        const int c  = idx / (VPB / 2);
        const int zp = idx % (VPB / 2);
        float2 v = make_float2(stA[2 * zp][c]     + stB[2 * zp][c],
                               stA[2 * zp + 1][c] + stB[2 * zp + 1][c]);
        __stcs((float2*)(ob + (size_t)c * NVOX + 2 * zp), v);
    }
}

// ---------------- launch ----------------
extern "C" void kernel_launch(void* const* d_in, const int* in_sizes, int n_in,
                              void* d_out, int out_size)
{
    const float* x3a = (const float*)d_in[0];
    const float* x3b = (const float*)d_in[1];
    const float* x2a = (const float*)d_in[2];
    const float* x2b = (const float*)d_in[3];
    const float* pp  = (const float*)d_in[4];
    float* out = (float*)d_out;

    __half* sptr = nullptr;
    cudaGetSymbolAddress((void**)&sptr, g_s);

    // pass 1: fused fold + transpose (3D + 2D in one launch)
    {
        dim3 blk(32, 8);
        dim3 grd(T3TILES + T2TILES, (CCH + 31) / 32, NB);  // 3000 x 7 x 2
        transpose_add_kernel<<<grd, blk>>>(x3a, x3b, x2a, x2b, sptr);
    }

    // pass 2: 2 warps per voxel
    {
        const int nblocks = NB * XDIM * YDIM * ZCH;  // 25920
        sample_kernel<<<nblocks, 640>>>(pp, out);
    }
}

// round 12
// speedup vs baseline: 1.2635x; 1.2635x over previous
#include <cuda_runtime.h>
#include <cuda_fp16.h>
#include <cstdint>

// ---------------- problem constants ----------------
#define CCH   200               // channels
#define NC8   25                // uint4 (8-half) chunks per position
#define D3    16
#define H3    60
#define W3    80
#define P3    (D3*H3*W3)        // 76800
#define H2    120
#define W2    160
#define P2    (H2*W2)           // 19200
#define XDIM  60
#define YDIM  36
#define ZDIM  60
#define NVOX  (XDIM*YDIM*ZDIM)  // 129600
#define NB    2
#define VPB   10                // voxels per block
#define ZCH   (ZDIM/VPB)        // 6

#define T3TILES (P3/32)         // 2400
#define T2TILES (P2/32)         // 600
#define S2BASE  (P3 * NC8 * NB) // uint4-chunk offset of 2D region (per-batch below)

// channel-last fp16 scratch: s3[b][pos][c] then s2[b][pos][c]
__device__ __align__(16) __half g_s3[NB * P3 * CCH];   // 61.4 MB
__device__ __align__(16) __half g_s2[NB * P2 * CCH];   // 15.4 MB

// ---------------- pass 1: fused add + transpose, ONE batch ----------------
__global__ void transpose_add_kernel(const float* __restrict__ a3,
                                     const float* __restrict__ b3,
                                     const float* __restrict__ a2,
                                     const float* __restrict__ b2,
                                     __half* __restrict__ d3,
                                     __half* __restrict__ d2,
                                     int batch)
{
    __shared__ float tile[32][33];
    int pt = blockIdx.x;
    const int ct = blockIdx.y;

    const float *ab, *bb;
    __half* db;
    int P;
    if (pt < T3TILES) {
        P  = P3;
        ab = a3 + (size_t)batch * CCH * P3;
        bb = b3 + (size_t)batch * CCH * P3;
        db = d3 + (size_t)batch * P3 * CCH;
    } else {
        pt -= T3TILES;
        P  = P2;
        ab = a2 + (size_t)batch * CCH * P2;
        bb = b2 + (size_t)batch * CCH * P2;
        db = d2 + (size_t)batch * P2 * CCH;
    }

    const int p0 = pt * 32, c0 = ct * 32;
    const int tx = threadIdx.x, ty = threadIdx.y;   // 32 x 8

    #pragma unroll
    for (int i = 0; i < 32; i += 8) {
        int c = c0 + ty + i;
        int p = p0 + tx;
        if (c < CCH)
            tile[ty + i][tx] = ab[(size_t)c * P + p] + bb[(size_t)c * P + p];
    }
    __syncthreads();
    #pragma unroll
    for (int i = 0; i < 32; i += 8) {
        int p = p0 + ty + i;
        int c = c0 + tx;
        if (c < CCH)
            db[(size_t)p * CCH + c] = __float2half_rn(tile[tx][ty + i]);
    }
}

// ---------------- pass 2: R7 sample kernel, ONE batch ----------------
__global__ void __launch_bounds__(256) sample_kernel(const float* __restrict__ pp,
                                                     float* __restrict__ out,
                                                     int b)
{
    __shared__ int   sm_off[VPB][12];    // uint4-index incl. batch base
    __shared__ float sm_w[VPB][12];
    __shared__ float st[VPB][204];       // staged results

    const int bid = blockIdx.x;
    const int zc  = bid % ZCH;
    int rest      = bid / ZCH;
    const int y   = rest % YDIM; rest /= YDIM;
    const int x   = rest;                // 0..59
    const int z0  = zc * VPB;
    const int tid = threadIdx.x;

    // ---------- Phase A: tap setup (one thread per voxel-tap) ----------
    if (tid < VPB * 12) {
        const int q = tid / 12;
        const int t = tid % 12;          // 0..7 = 3D, 8..11 = 2D
        const int z = z0 + q;
        const int v = x * (ZDIM * YDIM) + z * YDIM + y;
        const float* g = pp + ((size_t)b * NVOX + v) * 3;
        const float px = __ldg(g + 0), py = __ldg(g + 1);

        int offset; float weight;
        if (t < 8) {
            const float pz = __ldg(g + 2);
            const float gx = (px + 1.f) * 0.5f * (W3 - 1);
            const float gy = (py + 1.f) * 0.5f * (H3 - 1);
            const float gz = (pz + 1.f) * 0.5f * (D3 - 1);
            const float fx = floorf(gx), fy = floorf(gy), fz = floorf(gz);
            const float wx = gx - fx, wy = gy - fy, wz = gz - fz;
            const int dx = t & 1, dy = (t >> 1) & 1, dz = (t >> 2) & 1;
            const int xi = (int)fx + dx, yi = (int)fy + dy, zi = (int)fz + dz;
            const bool valid = (xi >= 0) & (xi < W3) & (yi >= 0) & (yi < H3) &
                               (zi >= 0) & (zi < D3);
            const int xc = min(max(xi, 0), W3 - 1);
            const int yc = min(max(yi, 0), H3 - 1);
            const int zcv = min(max(zi, 0), D3 - 1);
            const int pos = (zcv * H3 + yc) * W3 + xc;
            offset = b * (P3 * NC8) + pos * NC8;
            float w = (dx ? wx : 1.f - wx) * (dy ? wy : 1.f - wy) *
                      (dz ? wz : 1.f - wz);
            weight = valid ? w : 0.f;
        } else {
            const float gx = (px + 1.f) * 0.5f * (W2 - 1);
            const float gy = (py + 1.f) * 0.5f * (H2 - 1);
            const float fx = floorf(gx), fy = floorf(gy);
            const float wx = gx - fx, wy = gy - fy;
            const int tt = t - 8;
            const int dx = tt & 1, dy = (tt >> 1) & 1;
            const int xi = (int)fx + dx, yi = (int)fy + dy;
            const bool valid = (xi >= 0) & (xi < W2) & (yi >= 0) & (yi < H2);
            const int xc = min(max(xi, 0), W2 - 1);
            const int yc = min(max(yi, 0), H2 - 1);
            const int pos = yc * W2 + xc;
            offset = b * (P2 * NC8) + pos * NC8;
            float w = (dx ? wx : 1.f - wx) * (dy ? wy : 1.f - wy);
            weight = valid ? w : 0.f;
        }
        sm_off[q][t] = offset;
        sm_w[q][t]   = weight;
    }
    __syncthreads();

    // ---------- Phase B: gather (fp16 taps, fp32 accum) ----------
    if (tid < VPB * NC8) {               // 250 active
        const int q  = tid / NC8;
        const int cc = tid % NC8;
        const uint4* s3 = (const uint4*)g_s3;
        const uint4* s2 = (const uint4*)g_s2;

        float ax = 0.f, ay = 0.f, az = 0.f, aw = 0.f;
        float bx = 0.f, by = 0.f, bz = 0.f, bw = 0.f;
        #pragma unroll
        for (int t = 0; t < 12; t++) {
            const uint4 vv = (t < 8) ? s3[sm_off[q][t] + cc]
                                     : s2[sm_off[q][t] + cc];
            const float w = sm_w[q][t];
            const __half2* h = (const __half2*)&vv;
            const float2 f0 = __half22float2(h[0]);
            const float2 f1 = __half22float2(h[1]);
            const float2 f2 = __half22float2(h[2]);
            const float2 f3 = __half22float2(h[3]);
            ax += w * f0.x; ay += w * f0.y;
            az += w * f1.x; aw += w * f1.y;
            bx += w * f2.x; by += w * f2.y;
            bz += w * f3.x; bw += w * f3.y;
        }
        *(float4*)&st[q][cc * 8]     = make_float4(ax, ay, az, aw);
        *(float4*)&st[q][cc * 8 + 4] = make_float4(bx, by, bz, bw);
    }
    __syncthreads();

    // ---------- Phase C: coalesced write-out: out[b][c][x][y][z] ----------
    float* ob = out + (size_t)b * CCH * NVOX +
                ((size_t)x * YDIM + y) * ZDIM + z0;
    for (int idx = tid; idx < CCH * (VPB / 2); idx += 256) {
        const int c  = idx / (VPB / 2);
        const int zp = idx % (VPB / 2);
        float2 v = make_float2(st[2 * zp][c], st[2 * zp + 1][c]);
        __stcs((float2*)(ob + (size_t)c * NVOX + 2 * zp), v);
    }
}

// ---------------- host-side stream/event objects (static init, host-only) --
struct PipeObjs {
    cudaStream_t side;
    cudaEvent_t  ev_fork, ev_t1;
    PipeObjs() {
        cudaStreamCreateWithFlags(&side, cudaStreamNonBlocking);
        cudaEventCreateWithFlags(&ev_fork, cudaEventDisableTiming);
        cudaEventCreateWithFlags(&ev_t1,   cudaEventDisableTiming);
    }
};
static PipeObjs g_pipe;

// ---------------- launch: batch-pipelined ----------------
extern "C" void kernel_launch(void* const* d_in, const int* in_sizes, int n_in,
                              void* d_out, int out_size)
{
    const float* x3a = (const float*)d_in[0];
    const float* x3b = (const float*)d_in[1];
    const float* x2a = (const float*)d_in[2];
    const float* x2b = (const float*)d_in[3];
    const float* pp  = (const float*)d_in[4];
    float* out = (float*)d_out;

    __half* s3ptr = nullptr;
    __half* s2ptr = nullptr;
    cudaGetSymbolAddress((void**)&s3ptr, g_s3);
    cudaGetSymbolAddress((void**)&s2ptr, g_s2);

    const dim3 tblk(32, 8);
    const dim3 tgrd(T3TILES + T2TILES, (CCH + 31) / 32, 1);  // 3000 x 7
    const int  sblocks = XDIM * YDIM * ZCH;                   // 12960

    // main: T(b0)
    transpose_add_kernel<<<tgrd, tblk>>>(x3a, x3b, x2a, x2b, s3ptr, s2ptr, 0);
    cudaEventRecord(g_pipe.ev_fork, 0);

    // side: T(b1) after T(b0) issues (overlaps with S(b0))
    cudaStreamWaitEvent(g_pipe.side, g_pipe.ev_fork, 0);
    transpose_add_kernel<<<tgrd, tblk, 0, g_pipe.side>>>(x3a, x3b, x2a, x2b,
                                                         s3ptr, s2ptr, 1);
    cudaEventRecord(g_pipe.ev_t1, g_pipe.side);

    // main: S(b0) — depends only on T(b0), runs concurrent with T(b1)
    sample_kernel<<<sblocks, 256>>>(pp, out, 0);

    // main: join T(b1), then S(b1)
    cudaStreamWaitEvent(0, g_pipe.ev_t1, 0);
    sample_kernel<<<sblocks, 256>>>(pp, out, 1);
}